// round 9
// baseline (speedup 1.0000x reference)
#include <cuda_runtime.h>
#include <cstdint>
#include <math.h>

// Problem constants
#define CC      512
#define BB      16
#define TT      60
#define NP      196
#define NHEADS  4
#define HD      128
#define CLIPL   6
#define NFRAMES 36
#define TOPK    6
#define TOPM    12

// Output layout (flat float32):
//   [0]       audio_top_k        (16,36,512)
//   [294912]  visual_patch_top_m (16,36,12,512)
//   [3833856] visual_patch_feat  (16,432,512)  (identical bytes)
#define OFF1 294912
#define OFF2 3833856

// k_q block roles (R5-proven shape)
#define NB_QROWS  128    // 128 blocks x 4 warps = 512 rows (warp per row)
#define NB_AUDIO  72     // audio gather, 8 (b,f) rows each
#define NB_PREF   24     // L2 prefetch: Wk (1MB) + score-phase patch rows
#define NB_Q      (NB_QROWS + NB_AUDIO + NB_PREF)   // 224

// Scratch (device globals)
__device__ float g_q[CC];
__device__ float g_r[NHEADS * CC];
__device__ int   g_pid;

// ===========================================================================
// K1: q (warp per row) + audio gather + L2 prefetch for later kernels
// ===========================================================================
__global__ void __launch_bounds__(128)
k_q(const float* __restrict__ audio,
    const float* __restrict__ patch,
    const float* __restrict__ qst,
    const int*   __restrict__ topk,
    const float* __restrict__ in_w,
    const float* __restrict__ in_b,
    float*       __restrict__ out) {
    const int bid  = blockIdx.x;
    const int t    = threadIdx.x;
    const int warp = t >> 5, lane = t & 31;

    // ----------------- q rows: one warp per output row ---------------------
    if (bid < NB_QROWS) {
        const int row = bid * 4 + warp;           // 0..511
        const float4* x4 = (const float4*)qst;    // batch 0
        const float4* w4 = (const float4*)(in_w + (size_t)row * CC);
        float acc = 0.f;
        #pragma unroll
        for (int i = 0; i < 4; i++) {
            float4 a = w4[lane + 32 * i];
            float4 x = x4[lane + 32 * i];
            acc += a.x * x.x + a.y * x.y + a.z * x.z + a.w * x.w;
        }
        #pragma unroll
        for (int o = 16; o; o >>= 1) acc += __shfl_down_sync(0xffffffffu, acc, o);
        if (lane == 0) g_q[row] = acc + in_b[row];
        return;
    }

    // ----------------- audio gather (pid-independent) ----------------------
    if (bid < NB_QROWS + NB_AUDIO) {
        const int ab = bid - NB_QROWS;
        const float4* a4 = (const float4*)audio;
        float4*       o4 = (float4*)out;
        #pragma unroll
        for (int k = 0; k < 8; k++) {
            const int bf = ab * 8 + k;
            const int b = bf / NFRAMES, f = bf % NFRAMES;
            const int seg   = topk[b * TOPK + f / CLIPL];
            const int frame = seg * CLIPL + (f % CLIPL);
            o4[(size_t)bf * 128 + t] = a4[((size_t)b * TT + frame) * 128 + t];
        }
        return;
    }

    // ----------------- prefetch: Wk (rows 512..1023) + score patch rows ----
    {
        const int pb  = bid - NB_QROWS - NB_AUDIO;     // 0..23
        const int tid = pb * 128 + t;                  // 0..3071
        const int NTH = NB_PREF * 128;

        // Wk: 1MB = 8192 x 128B lines
        const char* wk = (const char*)(in_w + (size_t)CC * CC);
        for (int i = tid; i < 8192; i += NTH) {
            asm volatile("prefetch.global.L2 [%0];" :: "l"(wk + (size_t)i * 128));
        }
        // patch rows for scores: 196*512*4B = 3136 x 128B lines
        const int f0 = topk[0] * CLIPL;
        const char* pr = (const char*)(patch + (size_t)f0 * NP * CC);
        for (int i = tid; i < 3136; i += NTH) {
            asm volatile("prefetch.global.L2 [%0];" :: "l"(pr + (size_t)i * 128));
        }
    }
}

// ===========================================================================
// K2: r_h[c] = sum_j Wk[h*128+j, c] * q[h*128+j]
//     64 blocks = 4 heads x 16 col-slices (32 cols), j split across 8 warps.
// ===========================================================================
__global__ void __launch_bounds__(256)
k_r(const float* __restrict__ in_w) {
    __shared__ float sh_q[HD];
    __shared__ float sh_p[8][32];

    const int h  = blockIdx.x >> 4;            // head
    const int cb = (blockIdx.x & 15) * 32;     // col base
    const int t  = threadIdx.x;
    const int warp = t >> 5, lane = t & 31;

    if (t < HD) sh_q[t] = g_q[h * HD + t];
    __syncthreads();

    const float* Wk = in_w + (size_t)(CC + h * HD + warp * 16) * CC + cb + lane;
    float acc = 0.f;
    #pragma unroll
    for (int j = 0; j < 16; j++)
        acc += Wk[(size_t)j * CC] * sh_q[warp * 16 + j];
    sh_p[warp][lane] = acc;
    __syncthreads();

    if (t < 32) {
        float s = 0.f;
        #pragma unroll
        for (int w = 0; w < 8; w++) s += sh_p[w][t];
        g_r[h * CC + cb + t] = s;
    }
}

// ===========================================================================
// K3: scores (196 x 4 heads) + softmax + top-12 select + bcast-row prefetch
// ===========================================================================
__global__ void __launch_bounds__(1024)
k_scorepid(const float* __restrict__ patch, const int* __restrict__ topk) {
    __shared__ float sh_r[NHEADS * CC];
    __shared__ float s_sc[NHEADS * NP];
    __shared__ float s_w[NP];
    __shared__ float s_mx[NHEADS], s_inv[NHEADS];
    __shared__ int   s_pid;

    const int t = threadIdx.x;
    const int warp = t >> 5, lane = t & 31;

    sh_r[t] = g_r[t];
    sh_r[t + 1024] = g_r[t + 1024];
    if (t == 0) s_pid = -1;
    __syncthreads();

    // scores: warp per patch, strided over 32 warps (L2-warm from prefetch)
    const int f0 = topk[0] * CLIPL;
    const float4* p4 = (const float4*)(patch + (size_t)f0 * NP * CC);
    const float4* r4 = (const float4*)sh_r;
    for (int n = warp; n < NP; n += 32) {
        float4 xv[4];
        #pragma unroll
        for (int i = 0; i < 4; i++) xv[i] = p4[(size_t)n * 128 + lane + 32 * i];
        float acc[NHEADS] = {0.f, 0.f, 0.f, 0.f};
        #pragma unroll
        for (int h = 0; h < NHEADS; h++)
            #pragma unroll
            for (int i = 0; i < 4; i++) {
                float4 rv = r4[h * 128 + lane + 32 * i];
                acc[h] += rv.x * xv[i].x + rv.y * xv[i].y +
                          rv.z * xv[i].z + rv.w * xv[i].w;
            }
        #pragma unroll
        for (int h = 0; h < NHEADS; h++) {
            float v = acc[h];
            #pragma unroll
            for (int o = 16; o; o >>= 1) v += __shfl_down_sync(0xffffffffu, v, o);
            if (lane == 0) s_sc[h * NP + n] = 0.08838834764831845f * v;
        }
    }
    __syncthreads();

    // per-head softmax stats (warp per head)
    if (warp < NHEADS) {
        float m = -1e30f;
        for (int n = lane; n < NP; n += 32) m = fmaxf(m, s_sc[warp * NP + n]);
        #pragma unroll
        for (int o = 16; o; o >>= 1) m = fmaxf(m, __shfl_xor_sync(0xffffffffu, m, o));
        float s = 0.f;
        for (int n = lane; n < NP; n += 32) s += expf(s_sc[warp * NP + n] - m);
        #pragma unroll
        for (int o = 16; o; o >>= 1) s += __shfl_xor_sync(0xffffffffu, s, o);
        if (lane == 0) { s_mx[warp] = m; s_inv[warp] = 1.f / s; }
    }
    __syncthreads();

    // mean-over-heads softmax weights
    if (t < NP) {
        float acc = 0.f;
        #pragma unroll
        for (int h = 0; h < NHEADS; h++)
            acc += expf(s_sc[h * NP + t] - s_mx[h]) * s_inv[h];
        s_w[t] = acc * 0.25f;
    }
    __syncthreads();

    // pid = max index among top-12 (stable-argsort tie-break)
    if (t < NP) {
        const float wn = s_w[t];
        int cnt = 0;
        for (int m = 0; m < NP; m++)
            cnt += (s_w[m] > wn) || (s_w[m] == wn && m > t);
        if (cnt < TOPM) atomicMax(&s_pid, t);
    }
    __syncthreads();
    if (t == 0) g_pid = s_pid;
    __syncthreads();

    // prefetch the 576 bcast source rows (1.15MB) into L2 for k_bcast
    {
        const int pid = s_pid;
        for (int idx = t; idx < 576 * 16; idx += 1024) {
            const int bf = idx >> 4, line = idx & 15;
            const int b = bf / NFRAMES, f = bf % NFRAMES;
            const int seg   = topk[b * TOPK + f / CLIPL];
            const int frame = seg * CLIPL + (f % CLIPL);
            const char* p = (const char*)(patch +
                (((size_t)b * TT + frame) * NP + pid) * CC) + (size_t)line * 128;
            asm volatile("prefetch.global.L2 [%0];" :: "l"(p));
        }
    }
}

// ===========================================================================
// K4: pid-dependent broadcast via cp.async.bulk (TMA shared->global).
//     Block per bf: replicate 2KB row 12x in SMEM, then 2 bulk copies of 24KB.
// ===========================================================================
__global__ void __launch_bounds__(128)
k_bcast(const float* __restrict__ patch, const int* __restrict__ topk,
        float* __restrict__ out) {
    __shared__ alignas(128) float4 buf[TOPM * 128];   // 24KB

    const int bf = blockIdx.x;              // 0..575
    const int t  = threadIdx.x;             // 0..127
    const int b = bf / NFRAMES, f = bf % NFRAMES;
    const int seg   = topk[b * TOPK + f / CLIPL];
    const int frame = seg * CLIPL + (f % CLIPL);
    const int pid = g_pid;

    const float4* p4 = (const float4*)patch;
    const float4 p = p4[(((size_t)b * TT + frame) * NP + pid) * 128 + t];
    #pragma unroll
    for (int m = 0; m < TOPM; m++)
        buf[m * 128 + t] = p;
    __syncthreads();

    if (t == 0) {
        asm volatile("fence.proxy.async.shared::cta;" ::: "memory");
        unsigned int saddr;
        asm("{ .reg .u64 tmp; cvta.to.shared.u64 tmp, %1; cvt.u32.u64 %0, tmp; }"
            : "=r"(saddr) : "l"((const void*)buf));
        const float* dst1 = out + OFF1 + (size_t)bf * TOPM * CC;
        const float* dst2 = out + OFF2 + (size_t)bf * TOPM * CC;
        const unsigned int bytes = TOPM * CC * 4;    // 24576
        asm volatile("cp.async.bulk.global.shared::cta.bulk_group [%0], [%1], %2;"
                     :: "l"(dst1), "r"(saddr), "r"(bytes) : "memory");
        asm volatile("cp.async.bulk.global.shared::cta.bulk_group [%0], [%1], %2;"
                     :: "l"(dst2), "r"(saddr), "r"(bytes) : "memory");
        asm volatile("cp.async.bulk.commit_group;" ::: "memory");
        asm volatile("cp.async.bulk.wait_group 0;" ::: "memory");
    }
}

// ---------------------------------------------------------------------------
extern "C" void kernel_launch(void* const* d_in, const int* in_sizes, int n_in,
                              void* d_out, int out_size) {
    const float* audio = (const float*)d_in[0];   // (16,60,512)
    const float* patch = (const float*)d_in[1];   // (16,60,196,512)
    const float* qst   = (const float*)d_in[2];   // (16,512)
    const int*   topk  = (const int*)  d_in[3];   // (16,1,6)
    const float* in_w  = (const float*)d_in[4];   // (1536,512)
    const float* in_b  = (const float*)d_in[5];   // (1536,)
    float* out = (float*)d_out;

    k_q<<<NB_Q, 128>>>(audio, patch, qst, topk, in_w, in_b, out);
    k_r<<<64, 256>>>(in_w);
    k_scorepid<<<1, 1024>>>(patch, topk);
    k_bcast<<<BB * NFRAMES, 128>>>(patch, topk, out);
}

// round 10
// speedup vs baseline: 1.3944x; 1.3944x over previous
#include <cuda_runtime.h>
#include <cstdint>
#include <math.h>

// Problem constants
#define CC      512
#define BB      16
#define TT      60
#define NP      196
#define NHEADS  4
#define HD      128
#define CLIPL   6
#define NFRAMES 36
#define TOPK    6
#define TOPM    12

// Output layout (flat float32)
#define OFF1 294912
#define OFF2 3833856

// Block-role layout: producers FIRST (wave-1 scheduling guarantees progress)
#define NB_Q    64                     // q: 64 blocks x 8 warps = 512 rows
#define NB_R    64                     // r: 4 heads x 16 col-slices
#define NB_S    8                      // scores: 8 blocks x 8 warps
#define NB_AUD  36                     // audio gather + score-row prefetch
#define NB_BC   576                    // broadcast
#define B_Q     0
#define B_R     (B_Q + NB_Q)           // 64
#define B_S     (B_R + NB_R)           // 128
#define B_P     (B_S + NB_S)           // 136 (pid block)
#define B_A     (B_P + 1)              // 137
#define B_B     (B_A + NB_AUD)         // 173
#define NB_TOT  (B_B + NB_BC)          // 749

// Scratch + sync (device globals; counters returned to 0 every launch)
__device__ float g_q[CC];
__device__ float g_r[NHEADS * CC];
__device__ float g_sc[NHEADS * NP];
__device__ int   g_pid;
__device__ int   c_q, c_qd;      // q produced (64) / consumed by r (64)
__device__ int   c_r, c_rd;      // r produced (64) / consumed by score (8)
__device__ int   c_s;            // score produced (8), sole consumer = pid
__device__ int   g_pflag, c_pd;  // pid flag / consumed by bcast (576)

// ---- sync helpers ---------------------------------------------------------
__device__ __forceinline__ void spin_wait(volatile int* p, int target, int ns) {
    if (threadIdx.x == 0) { while (*p < target) __nanosleep(ns); }
    __syncthreads();
    __threadfence();                  // acquire
}
__device__ __forceinline__ void signal(int* c) {
    __syncthreads();
    __threadfence();                  // release
    if (threadIdx.x == 0) atomicAdd(c, 1);
}
__device__ __forceinline__ void consume_reset(int* cd, int n, int* cp) {
    if (threadIdx.x == 0)
        if (atomicAdd(cd, 1) == n - 1) { *cp = 0; *cd = 0; }
}

// ===========================================================================
__global__ void __launch_bounds__(256)
fused(const float* __restrict__ audio,
      const float* __restrict__ patch,
      const float* __restrict__ qst,
      const int*   __restrict__ topk,
      const float* __restrict__ in_w,
      const float* __restrict__ in_b,
      float*       __restrict__ out) {
    __shared__ float S[1100];          // role-shared scratch (4.4KB)
    __shared__ int   s_pid;

    const int bid  = blockIdx.x;
    const int t    = threadIdx.x;
    const int warp = t >> 5, lane = t & 31;

    // ========================= Q blocks (bids 0..63) ========================
    if (bid < B_R) {
        const int row = bid * 8 + warp;            // 0..511, warp per row
        const float4* x4 = (const float4*)qst;     // batch 0
        const float4* w4 = (const float4*)(in_w + (size_t)row * CC);
        float acc = 0.f;
        #pragma unroll
        for (int i = 0; i < 4; i++) {
            float4 a = w4[lane + 32 * i];
            float4 x = x4[lane + 32 * i];
            acc += a.x * x.x + a.y * x.y + a.z * x.z + a.w * x.w;
        }
        #pragma unroll
        for (int o = 16; o; o >>= 1) acc += __shfl_down_sync(0xffffffffu, acc, o);
        if (lane == 0) g_q[row] = acc + in_b[row];
        signal(&c_q);
        return;
    }

    // ========================= R blocks (64..127) ===========================
    if (bid < B_S) {
        const int rid = bid - B_R;
        const int h   = rid >> 4;                  // head
        const int cb  = (rid & 15) * 32;           // col base

        // PREWORK: issue all 16 Wk loads (independent of q) before polling
        const float* Wk = in_w + (size_t)(CC + h * HD + warp * 16) * CC + cb + lane;
        float wk[16];
        #pragma unroll
        for (int j = 0; j < 16; j++) wk[j] = Wk[(size_t)j * CC];

        spin_wait(&c_q, NB_Q, 64);
        consume_reset(&c_qd, NB_R, &c_q);

        float acc = 0.f;
        #pragma unroll
        for (int j = 0; j < 16; j++)
            acc += wk[j] * g_q[h * HD + warp * 16 + j];   // warp-uniform loads
        S[warp * 32 + lane] = acc;
        __syncthreads();
        if (t < 32) {
            float s = 0.f;
            #pragma unroll
            for (int w = 0; w < 8; w++) s += S[w * 32 + t];
            g_r[h * CC + cb + t] = s;
        }
        signal(&c_r);
        return;
    }

    // ========================= SCORE blocks (128..135) ======================
    if (bid < B_P) {
        const int gw = (bid - B_S) * 8 + warp;     // global warp 0..63
        const int f0 = topk[0] * CLIPL;
        const float4* p4 = (const float4*)(patch + (size_t)f0 * NP * CC);

        // PREWORK: first patch row (independent of r) before polling
        float4 xv0[4];
        #pragma unroll
        for (int i = 0; i < 4; i++) xv0[i] = p4[(size_t)gw * 128 + lane + 32 * i];

        spin_wait(&c_r, NB_R, 64);
        consume_reset(&c_rd, NB_S, &c_r);

        const float4* r4 = (const float4*)g_r;
        for (int pi = 0; pi < 4; pi++) {
            const int n = gw + 64 * pi;
            if (n >= NP) break;
            float4 xv[4];
            if (pi == 0) {
                #pragma unroll
                for (int i = 0; i < 4; i++) xv[i] = xv0[i];
            } else {
                #pragma unroll
                for (int i = 0; i < 4; i++) xv[i] = p4[(size_t)n * 128 + lane + 32 * i];
            }
            float acc[NHEADS] = {0.f, 0.f, 0.f, 0.f};
            #pragma unroll
            for (int h = 0; h < NHEADS; h++)
                #pragma unroll
                for (int i = 0; i < 4; i++) {
                    float4 rv = r4[h * 128 + lane + 32 * i];
                    acc[h] += rv.x * xv[i].x + rv.y * xv[i].y +
                              rv.z * xv[i].z + rv.w * xv[i].w;
                }
            #pragma unroll
            for (int h = 0; h < NHEADS; h++) {
                float v = acc[h];
                #pragma unroll
                for (int o = 16; o; o >>= 1) v += __shfl_down_sync(0xffffffffu, v, o);
                if (lane == 0) g_sc[h * NP + n] = 0.08838834764831845f * v;
            }
        }
        signal(&c_s);
        return;
    }

    // ========================= PID block (136) ==============================
    if (bid == B_P) {
        if (t == 0) s_pid = -1;
        spin_wait(&c_s, NB_S, 64);
        if (t == 0) c_s = 0;                       // sole consumer resets

        for (int idx = t; idx < NHEADS * NP; idx += 256) S[idx] = g_sc[idx];
        __syncthreads();

        // per-head softmax stats (warps 0-3)
        if (warp < NHEADS) {
            float m = -1e30f;
            for (int n = lane; n < NP; n += 32) m = fmaxf(m, S[warp * NP + n]);
            #pragma unroll
            for (int o = 16; o; o >>= 1) m = fmaxf(m, __shfl_xor_sync(0xffffffffu, m, o));
            float s = 0.f;
            for (int n = lane; n < NP; n += 32) s += expf(S[warp * NP + n] - m);
            #pragma unroll
            for (int o = 16; o; o >>= 1) s += __shfl_xor_sync(0xffffffffu, s, o);
            if (lane == 0) { S[1024 + warp] = m; S[1028 + warp] = 1.f / s; }
        }
        __syncthreads();

        // mean-over-heads weights -> S[800..995]
        if (t < NP) {
            float acc = 0.f;
            #pragma unroll
            for (int h = 0; h < NHEADS; h++)
                acc += expf(S[h * NP + t] - S[1024 + h]) * S[1028 + h];
            S[800 + t] = acc * 0.25f;
        }
        __syncthreads();

        // pid = max index among top-12 (stable-argsort tie-break)
        if (t < NP) {
            const float wn = S[800 + t];
            int cnt = 0;
            for (int m = 0; m < NP; m++)
                cnt += (S[800 + m] > wn) || (S[800 + m] == wn && m > t);
            if (cnt < TOPM) atomicMax(&s_pid, t);
        }
        __syncthreads();
        if (t == 0) {
            g_pid = s_pid;
            __threadfence();
            atomicExch(&g_pflag, 1);
        }
        return;
    }

    // ========================= AUDIO blocks (137..172) ======================
    if (bid < B_B) {
        const int ab = bid - B_A;
        const float4* a4 = (const float4*)audio;
        float4*       o4 = (float4*)out;
        const int tl = t & 127;
        #pragma unroll
        for (int k = 0; k < 8; k++) {
            const int bf = ab * 16 + k * 2 + (t >> 7);
            const int b = bf / NFRAMES, f = bf % NFRAMES;
            const int seg   = topk[b * TOPK + f / CLIPL];
            const int frame = seg * CLIPL + (f % CLIPL);
            o4[(size_t)bf * 128 + tl] = a4[((size_t)b * TT + frame) * 128 + tl];
        }
        // prefetch score-phase patch rows (400KB) into L2
        const int tid = ab * 256 + t;              // 0..9215
        if (tid < 3136) {
            const int f0 = topk[0] * CLIPL;
            const char* pr = (const char*)(patch + (size_t)f0 * NP * CC);
            asm volatile("prefetch.global.L2 [%0];" :: "l"(pr + (size_t)tid * 128));
        }
        return;
    }

    // ========================= BCAST blocks (173..748) ======================
    {
        const int bf = bid - B_B;                  // 0..575
        const int b = bf / NFRAMES, f = bf % NFRAMES;
        const int seg   = topk[b * TOPK + f / CLIPL];
        const int frame = seg * CLIPL + (f % CLIPL);

        spin_wait(&g_pflag, 1, 256);
        const int pid = g_pid;

        const float4* p4 = (const float4*)patch;
        float4*       o4 = (float4*)out;
        const int tl = t & 127, reg = t >> 7;      // halves handle the 2 regions
        const float4 p = p4[(((size_t)b * TT + frame) * NP + pid) * 128 + tl];
        const size_t base = (reg ? OFF2 : OFF1) / 4 + (size_t)bf * TOPM * 128 + tl;
        #pragma unroll
        for (int m = 0; m < TOPM; m++)
            o4[base + (size_t)m * 128] = p;

        consume_reset(&c_pd, NB_BC, &g_pflag);
    }
}

// ---------------------------------------------------------------------------
extern "C" void kernel_launch(void* const* d_in, const int* in_sizes, int n_in,
                              void* d_out, int out_size) {
    const float* audio = (const float*)d_in[0];   // (16,60,512)
    const float* patch = (const float*)d_in[1];   // (16,60,196,512)
    const float* qst   = (const float*)d_in[2];   // (16,512)
    const int*   topk  = (const int*)  d_in[3];   // (16,1,6)
    const float* in_w  = (const float*)d_in[4];   // (1536,512)
    const float* in_b  = (const float*)d_in[5];   // (1536,)
    float* out = (float*)d_out;

    fused<<<NB_TOT, 256>>>(audio, patch, qst, topk, in_w, in_b, out);
}